// round 12
// baseline (speedup 1.0000x reference)
#include <cuda_runtime.h>
#include <cuda_fp16.h>
#include <math.h>
#include <stdint.h>

#define B_DIM 1024
#define V_DIM 50257
#define E_DIM 128
#define NB    393          // ceil(V/128)
#define NB4   1572         // NB*4 partials per row (per-warp granularity)
#define N4    12865792u    // B*V/4

// ---------------- scratch ----------------
__device__ int   g_ids[B_DIM];
__device__ float g_lse[B_DIM];
__device__ __align__(16) __half g_qh[B_DIM * E_DIM];
__device__ __align__(16) __half g_nh[V_DIM * E_DIM];
__device__ float g_pmax[B_DIM * NB4];
__device__ float g_psum[B_DIM * NB4];

// ---------------- helpers ----------------
__device__ __forceinline__ uint32_t smem_u32(const void* p) {
    uint32_t a;
    asm("{ .reg .u64 t; cvta.to.shared.u64 t, %1; cvt.u32.u64 %0, t; }" : "=r"(a) : "l"(p));
    return a;
}
__device__ __forceinline__ void ldmatrix_x4(uint32_t* r, uint32_t addr) {
    asm volatile("ldmatrix.sync.aligned.m8n8.x4.shared.b16 {%0,%1,%2,%3}, [%4];"
                 : "=r"(r[0]), "=r"(r[1]), "=r"(r[2]), "=r"(r[3]) : "r"(addr));
}
__device__ __forceinline__ void mma16816(float* d, const uint32_t* a, const uint32_t* b) {
    asm volatile(
        "mma.sync.aligned.m16n8k16.row.col.f32.f16.f16.f32 "
        "{%0,%1,%2,%3}, {%4,%5,%6,%7}, {%8,%9}, {%0,%1,%2,%3};"
        : "+f"(d[0]), "+f"(d[1]), "+f"(d[2]), "+f"(d[3])
        : "r"(a[0]), "r"(a[1]), "r"(a[2]), "r"(a[3]), "r"(b[0]), "r"(b[1]));
}

// smem layout (bytes): double-buffered A + single B
#define OFF_AH0  0          // 64x128 f16 = 16384
#define OFF_AH1  16384
#define OFF_BH   32768      // 128x128 f16 = 32768
#define SMEM_TOTAL 65536

// ---------------------------------------------------------------------------
// Kernel 1: find one-hot ids (flat float4)
// ---------------------------------------------------------------------------
__global__ void find_ids_kernel(const float4* __restrict__ xs) {
    unsigned i = blockIdx.x * 256u + threadIdx.x;     // < N4
    float4 v = __ldcs(&xs[i]);
    if (v.x != 0.f || v.y != 0.f || v.z != 0.f || v.w != 0.f) {
        unsigned base = i * 4u;
        if (v.x != 0.f) g_ids[ base      / V_DIM] =  base      % V_DIM;
        if (v.y != 0.f) g_ids[(base + 1) / V_DIM] = (base + 1) % V_DIM;
        if (v.z != 0.f) g_ids[(base + 2) / V_DIM] = (base + 2) % V_DIM;
        if (v.w != 0.f) g_ids[(base + 3) / V_DIM] = (base + 3) % V_DIM;
    }
}

// ---------------------------------------------------------------------------
// Kernel 2: gather + project + f16 convert, fused.
// ---------------------------------------------------------------------------
__global__ void gather_project_kernel(const float* __restrict__ EMBEDM,
                                      const float* __restrict__ metric) {
    __shared__ float s[E_DIM];
    int b = blockIdx.x, j = threadIdx.x;
    int id = g_ids[b];
    s[j] = EMBEDM[(size_t)id * E_DIM + j];
    __syncthreads();
    float acc = 0.0f;
#pragma unroll 16
    for (int e = 0; e < E_DIM; e++) acc += s[e] * metric[e * E_DIM + j];
    g_qh[b * E_DIM + j] = __float2half_rn(acc);
}

// ---------------------------------------------------------------------------
// Kernel 3: NEG f16 conversion (vectorized: float4 -> half2 x2)
// ---------------------------------------------------------------------------
__global__ void convert_neg_kernel(const float4* __restrict__ NEG) {
    int i = blockIdx.x * 256 + threadIdx.x;           // < V*E/4
    if (i < V_DIM * E_DIM / 4) {
        float4 x = __ldcs(&NEG[i]);
        __half2 h0 = __floats2half2_rn(x.x, x.y);
        __half2 h1 = __floats2half2_rn(x.z, x.w);
        *reinterpret_cast<uint2*>(&g_nh[i * 4]) =
            make_uint2(*(uint32_t*)&h0, *(uint32_t*)&h1);
    }
}

// ---------------------------------------------------------------------------
// Kernel 4: HMMA (mma.sync f16) GEMM + per-warp partial LSE (no epilogue smem).
// grid = (393, 4). 256 threads, 8 warps as 2(M) x 4(N), warp tile 32x32.
// A tiles double-buffered in smem; B tile loaded once per CTA.
// ---------------------------------------------------------------------------
__global__ void __launch_bounds__(256, 3) gemm_hmma_kernel(float* __restrict__ C) {
    extern __shared__ __align__(1024) char smem[];
    const uint32_t sb = smem_u32(smem);
    const int tid = threadIdx.x;
    const int lane = tid & 31;
    const int wid = tid >> 5;
    const int bn = blockIdx.x * 128;

    // ---- load B tile (128 rows x 128 k, f16), once per CTA ----
#pragma unroll
    for (int i = 0; i < 8; i++) {
        int idx = tid + i * 256;          // 0..2047
        int r = idx >> 4, c = idx & 15;
        int gn = bn + r;
        uint4 vh = make_uint4(0, 0, 0, 0);
        if (gn < V_DIM)
            vh = *reinterpret_cast<const uint4*>(&g_nh[(size_t)gn * E_DIM + c * 8]);
        uint32_t off = (uint32_t)((r << 8) + ((c ^ (r & 7)) << 4));
        *reinterpret_cast<uint4*>(smem + OFF_BH + off) = vh;
    }

    const int wm = (wid >> 2) * 32;
    const int wn = (wid & 3) * 32;

    // per-thread ldmatrix address precompute
    const int i8  = lane & 7;
    const int q   = lane >> 3;           // 0..3
    const int qhi = q >> 1;              // A: k-chunk-half select
    const int q2  = q & 1;               // B: k-chunk-half select
    uint32_t a_rowoff[2];
    int a7[2];
#pragma unroll
    for (int mf = 0; mf < 2; mf++) {
        int ar = wm + mf * 16 + i8 + ((q & 1) << 3);
        a_rowoff[mf] = (uint32_t)(ar << 8);
        a7[mf] = ar & 7;
    }
    // B: nf-pair packing — lanes 16-31 load the second nf of the pair
    uint32_t b_rowoff[2];
    int b7[2];
#pragma unroll
    for (int p = 0; p < 2; p++) {
        int br = wn + (p * 2 + (lane >> 4)) * 8 + i8;
        b_rowoff[p] = (uint32_t)(br << 8);
        b7[p] = br & 7;
    }

    // epilogue constants
    const int r_in = lane >> 2;          // 0..7
    const int cp   = lane & 3;           // col-pair
    const int pcol = blockIdx.x * 4 + (wid & 3);   // partial index (nb*4 + wni)
    bool cv[4][2];
#pragma unroll
    for (int nf = 0; nf < 4; nf++)
#pragma unroll
        for (int j = 0; j < 2; j++)
            cv[nf][j] = (bn + wn + nf * 8 + cp * 2 + j) < V_DIM;

    // A-tile loader (64 rows x 128 k, f16) into buffer `dst`
    auto load_A = [&](int bm, uint32_t dst) {
#pragma unroll
        for (int i = 0; i < 4; i++) {
            int idx = tid + i * 256;          // 0..1023
            int r = idx >> 4, c = idx & 15;
            uint32_t off = (uint32_t)((r << 8) + ((c ^ (r & 7)) << 4));
            *reinterpret_cast<uint4*>(smem + dst + off) =
                *reinterpret_cast<const uint4*>(&g_qh[(size_t)(bm + r) * E_DIM + c * 8]);
        }
    };

    const int bm0 = blockIdx.y * 4 * 64;
    load_A(bm0, OFF_AH0);
    __syncthreads();

    for (int mt = 0; mt < 4; mt++) {
        const int bm = bm0 + mt * 64;
        const uint32_t abuf = (mt & 1) ? OFF_AH1 : OFF_AH0;

        // prefetch next A tile into alternate buffer (overlaps mainloop+epilogue)
        if (mt < 3) load_A(bm + 64, (mt & 1) ? OFF_AH0 : OFF_AH1);

        float acc[2][4][4];
#pragma unroll
        for (int mf = 0; mf < 2; mf++)
#pragma unroll
            for (int nf = 0; nf < 4; nf++)
#pragma unroll
                for (int k = 0; k < 4; k++) acc[mf][nf][k] = 0.0f;

        // ---- mainloop: 4 LDSM + 8 HMMA per kk ----
#pragma unroll
        for (int kk = 0; kk < 8; kk++) {
            uint32_t ah[2][4];
#pragma unroll
            for (int mf = 0; mf < 2; mf++) {
                uint32_t chunk = (uint32_t)(((kk * 2 + qhi) ^ a7[mf]) << 4);
                ldmatrix_x4(ah[mf], sb + abuf + a_rowoff[mf] + chunk);
            }
            uint32_t bh[4][2];
#pragma unroll
            for (int p = 0; p < 2; p++) {
                uint32_t chunk = (uint32_t)(((kk * 2 + q2) ^ b7[p]) << 4);
                uint32_t th[4];
                ldmatrix_x4(th, sb + OFF_BH + b_rowoff[p] + chunk);
                bh[p * 2 + 0][0] = th[0]; bh[p * 2 + 0][1] = th[1];
                bh[p * 2 + 1][0] = th[2]; bh[p * 2 + 1][1] = th[3];
            }
#pragma unroll
            for (int mf = 0; mf < 2; mf++)
#pragma unroll
                for (int nf = 0; nf < 4; nf++)
                    mma16816(acc[mf][nf], ah[mf], bh[nf]);
        }

        // ---- epilogue: store C + per-warp partial LSE (no smem, no extra sync) ----
#pragma unroll
        for (int mf = 0; mf < 2; mf++) {
#pragma unroll
            for (int h = 0; h < 2; h++) {
                int tr  = wm + mf * 16 + h * 8 + r_in;       // tile row 0..63
                int row = bm + tr;
                float m = -INFINITY;
                const size_t rowbase = (size_t)row * V_DIM;
#pragma unroll
                for (int nf = 0; nf < 4; nf++) {
                    float v0 = acc[mf][nf][h * 2 + 0];
                    float v1 = acc[mf][nf][h * 2 + 1];
                    int col = bn + wn + nf * 8 + cp * 2;
                    if (cv[nf][0]) { __stcs(&C[rowbase + col], v0);     m = fmaxf(m, v0); }
                    if (cv[nf][1]) { __stcs(&C[rowbase + col + 1], v1); m = fmaxf(m, v1); }
                }
                // warp-local row reduce over the 4 cp lanes
                m = fmaxf(m, __shfl_xor_sync(0xFFFFFFFF, m, 1));
                m = fmaxf(m, __shfl_xor_sync(0xFFFFFFFF, m, 2));
                float s = 0.0f;
#pragma unroll
                for (int nf = 0; nf < 4; nf++) {
                    if (cv[nf][0]) s += __expf(acc[mf][nf][h * 2 + 0] - m);
                    if (cv[nf][1]) s += __expf(acc[mf][nf][h * 2 + 1] - m);
                }
                s += __shfl_xor_sync(0xFFFFFFFF, s, 1);
                s += __shfl_xor_sync(0xFFFFFFFF, s, 2);
                if (cp == 0) {
                    g_pmax[(size_t)row * NB4 + pcol] = m;
                    g_psum[(size_t)row * NB4 + pcol] = s;
                }
            }
        }
        __syncthreads();   // A-buffer reuse barrier (covers prefetch visibility too)
    }
}

// ---------------------------------------------------------------------------
// Kernel 5: reduce partial (max,sum) -> lse per row
// ---------------------------------------------------------------------------
__global__ void reduce_lse_kernel() {
    int b = blockIdx.x;
    int t = threadIdx.x;        // 128
    float m = -INFINITY, s = 0.0f;
    for (int i = t; i < NB4; i += 128) {
        float pm = g_pmax[(size_t)b * NB4 + i];
        float ps = g_psum[(size_t)b * NB4 + i];
        if (pm > m) { s = s * __expf(m - pm) + ps; m = pm; }
        else        { s += ps * __expf(pm - m); }
    }
#pragma unroll
    for (int o = 16; o > 0; o >>= 1) {
        float m2 = __shfl_xor_sync(0xFFFFFFFF, m, o);
        float s2 = __shfl_xor_sync(0xFFFFFFFF, s, o);
        float M = fmaxf(m, m2);
        s = s * __expf(m - M) + s2 * __expf(m2 - M);
        m = M;
    }
    __shared__ float sm[4], ss[4];
    if ((t & 31) == 0) { sm[t >> 5] = m; ss[t >> 5] = s; }
    __syncthreads();
    if (t == 0) {
        m = sm[0]; s = ss[0];
#pragma unroll
        for (int w = 1; w < 4; w++) {
            float M = fmaxf(m, sm[w]);
            s = s * __expf(m - M) + ss[w] * __expf(sm[w] - M);
            m = M;
        }
        g_lse[b] = m + logf(s);
    }
}

// ---------------------------------------------------------------------------
// Kernel 6: out -= lse[row]  (flat float4, streaming)
// ---------------------------------------------------------------------------
__global__ void sub_lse_kernel(float4* __restrict__ C) {
    unsigned i = blockIdx.x * 256u + threadIdx.x;   // < N4
    float4 v = __ldcs(&C[i]);
    unsigned base = i * 4u;
    v.x -= g_lse[ base      / V_DIM];
    v.y -= g_lse[(base + 1) / V_DIM];
    v.z -= g_lse[(base + 2) / V_DIM];
    v.w -= g_lse[(base + 3) / V_DIM];
    __stcs(&C[i], v);
}

// ---------------------------------------------------------------------------
extern "C" void kernel_launch(void* const* d_in, const int* in_sizes, int n_in,
                              void* d_out, int out_size) {
    const float* xs     = (const float*)d_in[0];
    const float* metric = (const float*)d_in[1];
    const float* EMBEDM = (const float*)d_in[2];
    const float* NEG    = (const float*)d_in[3];
    float* out = (float*)d_out;

    cudaFuncSetAttribute(gemm_hmma_kernel,
                         cudaFuncAttributeMaxDynamicSharedMemorySize, SMEM_TOTAL);

    find_ids_kernel<<<N4 / 256, 256>>>((const float4*)xs);
    gather_project_kernel<<<B_DIM, E_DIM>>>(EMBEDM, metric);
    convert_neg_kernel<<<(V_DIM * E_DIM / 4 + 255) / 256, 256>>>((const float4*)NEG);

    gemm_hmma_kernel<<<dim3(NB, 4), 256, SMEM_TOTAL>>>(out);

    reduce_lse_kernel<<<B_DIM, 128>>>();
    sub_lse_kernel<<<N4 / 256, 256>>>((float4*)out);
}

// round 15
// speedup vs baseline: 1.0077x; 1.0077x over previous
#include <cuda_runtime.h>
#include <cuda_fp16.h>
#include <math.h>
#include <stdint.h>

#define B_DIM 1024
#define V_DIM 50257
#define E_DIM 128
#define NBX   197          // ceil(V/256)
#define NB4   788          // NBX*4 partials per row (per-warp, 64-col granularity)
#define N4    12865792u    // B*V/4

// ---------------- scratch (small statics only — R13/R14 infra lesson) -------
__device__ int   g_ids[B_DIM];
__device__ float g_lse[B_DIM];
__device__ __align__(16) __half g_qh[B_DIM * E_DIM];
__device__ __align__(16) __half g_nh[V_DIM * E_DIM];
__device__ float g_pmax[B_DIM * NB4];
__device__ float g_psum[B_DIM * NB4];

// ---------------- helpers ----------------
__device__ __forceinline__ uint32_t smem_u32(const void* p) {
    uint32_t a;
    asm("{ .reg .u64 t; cvta.to.shared.u64 t, %1; cvt.u32.u64 %0, t; }" : "=r"(a) : "l"(p));
    return a;
}
__device__ __forceinline__ void ldmatrix_x4(uint32_t* r, uint32_t addr) {
    asm volatile("ldmatrix.sync.aligned.m8n8.x4.shared.b16 {%0,%1,%2,%3}, [%4];"
                 : "=r"(r[0]), "=r"(r[1]), "=r"(r[2]), "=r"(r[3]) : "r"(addr));
}
__device__ __forceinline__ void mma16816(float* d, const uint32_t* a, const uint32_t* b) {
    asm volatile(
        "mma.sync.aligned.m16n8k16.row.col.f32.f16.f16.f32 "
        "{%0,%1,%2,%3}, {%4,%5,%6,%7}, {%8,%9}, {%0,%1,%2,%3};"
        : "+f"(d[0]), "+f"(d[1]), "+f"(d[2]), "+f"(d[3])
        : "r"(a[0]), "r"(a[1]), "r"(a[2]), "r"(a[3]), "r"(b[0]), "r"(b[1]));
}

// smem layout (bytes): A (64x128 f16) + B (256x128 f16)
#define OFF_AH   0          // 16384
#define OFF_BH   16384      // 65536
#define SMEM_TOTAL 81920

// ---------------------------------------------------------------------------
// Kernel 1: find one-hot ids (flat float4)
// ---------------------------------------------------------------------------
__global__ void find_ids_kernel(const float4* __restrict__ xs) {
    unsigned i = blockIdx.x * 256u + threadIdx.x;     // < N4
    float4 v = __ldcs(&xs[i]);
    if (v.x != 0.f || v.y != 0.f || v.z != 0.f || v.w != 0.f) {
        unsigned base = i * 4u;
        if (v.x != 0.f) g_ids[ base      / V_DIM] =  base      % V_DIM;
        if (v.y != 0.f) g_ids[(base + 1) / V_DIM] = (base + 1) % V_DIM;
        if (v.z != 0.f) g_ids[(base + 2) / V_DIM] = (base + 2) % V_DIM;
        if (v.w != 0.f) g_ids[(base + 3) / V_DIM] = (base + 3) % V_DIM;
    }
}

// ---------------------------------------------------------------------------
// Kernel 2: gather + project + f16 convert, fused.
// ---------------------------------------------------------------------------
__global__ void gather_project_kernel(const float* __restrict__ EMBEDM,
                                      const float* __restrict__ metric) {
    __shared__ float s[E_DIM];
    int b = blockIdx.x, j = threadIdx.x;
    int id = g_ids[b];
    s[j] = EMBEDM[(size_t)id * E_DIM + j];
    __syncthreads();
    float acc = 0.0f;
#pragma unroll 16
    for (int e = 0; e < E_DIM; e++) acc += s[e] * metric[e * E_DIM + j];
    g_qh[b * E_DIM + j] = __float2half_rn(acc);
}

// ---------------------------------------------------------------------------
// Kernel 3: NEG f16 conversion (vectorized: float4 -> half2 x2)
// ---------------------------------------------------------------------------
__global__ void convert_neg_kernel(const float4* __restrict__ NEG) {
    int i = blockIdx.x * 256 + threadIdx.x;           // < V*E/4
    if (i < V_DIM * E_DIM / 4) {
        float4 x = __ldcs(&NEG[i]);
        __half2 h0 = __floats2half2_rn(x.x, x.y);
        __half2 h1 = __floats2half2_rn(x.z, x.w);
        *reinterpret_cast<uint2*>(&g_nh[i * 4]) =
            make_uint2(*(uint32_t*)&h0, *(uint32_t*)&h1);
    }
}

// ---------------------------------------------------------------------------
// Kernel 4: HMMA (mma.sync f16) GEMM + per-warp partial LSE.
// grid = (197, 4). 256 threads, 8 warps as 2(M) x 4(N), warp tile 32x64.
// CTA tile: M=64 (x4 mt loop = 256 rows), N=256. B in smem once per CTA.
// ---------------------------------------------------------------------------
__global__ void __launch_bounds__(256, 2) gemm_hmma_kernel(float* __restrict__ C) {
    extern __shared__ __align__(1024) char smem[];
    const uint32_t sb = smem_u32(smem);
    const int tid = threadIdx.x;
    const int lane = tid & 31;
    const int wid = tid >> 5;
    const int bn = blockIdx.x * 256;

    // ---- load B tile (256 rows x 128 k, f16), once per CTA ----
#pragma unroll
    for (int i = 0; i < 16; i++) {
        int idx = tid + i * 256;          // 0..4095
        int r = idx >> 4, c = idx & 15;
        int gn = bn + r;
        uint4 vh = make_uint4(0, 0, 0, 0);
        if (gn < V_DIM)
            vh = *reinterpret_cast<const uint4*>(&g_nh[(size_t)gn * E_DIM + c * 8]);
        uint32_t off = (uint32_t)((r << 8) + ((c ^ (r & 7)) << 4));
        *reinterpret_cast<uint4*>(smem + OFF_BH + off) = vh;
    }

    const int wm = (wid >> 2) * 32;      // M group: 0, 32
    const int wn = (wid & 3) * 64;       // N group: 0, 64, 128, 192

    // per-thread ldmatrix address precompute
    const int i8  = lane & 7;
    const int q   = lane >> 3;           // 0..3
    const int qhi = q >> 1;              // A: k-chunk-half select
    const int q2  = q & 1;               // B: k-chunk-half select
    uint32_t a_rowoff[2];
    int a7[2];
#pragma unroll
    for (int mf = 0; mf < 2; mf++) {
        int ar = wm + mf * 16 + i8 + ((q & 1) << 3);
        a_rowoff[mf] = (uint32_t)(ar << 8);
        a7[mf] = ar & 7;
    }
    // B: nf-pair packing — lanes 16-31 load the second nf of each pair
    uint32_t b_rowoff[4];
    int b7[4];
#pragma unroll
    for (int p = 0; p < 4; p++) {
        int br = wn + (p * 2 + (lane >> 4)) * 8 + i8;
        b_rowoff[p] = (uint32_t)(br << 8);
        b7[p] = br & 7;
    }

    // epilogue constants
    const int r_in = lane >> 2;          // 0..7
    const int cp   = lane & 3;           // col-pair
    const int pcol = blockIdx.x * 4 + (wid & 3);   // partial index
    bool cv[8][2];
#pragma unroll
    for (int nf = 0; nf < 8; nf++)
#pragma unroll
        for (int j = 0; j < 2; j++)
            cv[nf][j] = (bn + wn + nf * 8 + cp * 2 + j) < V_DIM;

    const int bm0 = blockIdx.y * 4 * 64;

    for (int mt = 0; mt < 4; mt++) {
        const int bm = bm0 + mt * 64;

        // ---- load A tile (64 rows x 128 k, f16) ----
#pragma unroll
        for (int i = 0; i < 4; i++) {
            int idx = tid + i * 256;          // 0..1023
            int r = idx >> 4, c = idx & 15;
            uint32_t off = (uint32_t)((r << 8) + ((c ^ (r & 7)) << 4));
            *reinterpret_cast<uint4*>(smem + OFF_AH + off) =
                *reinterpret_cast<const uint4*>(&g_qh[(size_t)(bm + r) * E_DIM + c * 8]);
        }
        __syncthreads();

        float acc[2][8][4];
#pragma unroll
        for (int mf = 0; mf < 2; mf++)
#pragma unroll
            for (int nf = 0; nf < 8; nf++)
#pragma unroll
                for (int k = 0; k < 4; k++) acc[mf][nf][k] = 0.0f;

        // ---- mainloop: 6 LDSM + 16 HMMA per kk ----
#pragma unroll
        for (int kk = 0; kk < 8; kk++) {
            uint32_t ah[2][4];
#pragma unroll
            for (int mf = 0; mf < 2; mf++) {
                uint32_t chunk = (uint32_t)(((kk * 2 + qhi) ^ a7[mf]) << 4);
                ldmatrix_x4(ah[mf], sb + OFF_AH + a_rowoff[mf] + chunk);
            }
            uint32_t bh[8][2];
#pragma unroll
            for (int p = 0; p < 4; p++) {
                uint32_t chunk = (uint32_t)(((kk * 2 + q2) ^ b7[p]) << 4);
                uint32_t th[4];
                ldmatrix_x4(th, sb + OFF_BH + b_rowoff[p] + chunk);
                bh[p * 2 + 0][0] = th[0]; bh[p * 2 + 0][1] = th[1];
                bh[p * 2 + 1][0] = th[2]; bh[p * 2 + 1][1] = th[3];
            }
#pragma unroll
            for (int mf = 0; mf < 2; mf++)
#pragma unroll
                for (int nf = 0; nf < 8; nf++)
                    mma16816(acc[mf][nf], ah[mf], bh[nf]);
        }

        // ---- epilogue: store C (streaming scalar: V odd) + per-warp partials ----
#pragma unroll
        for (int mf = 0; mf < 2; mf++) {
#pragma unroll
            for (int h = 0; h < 2; h++) {
                int tr  = wm + mf * 16 + h * 8 + r_in;       // tile row 0..63
                int row = bm + tr;
                float m = -INFINITY;
                const size_t rowbase = (size_t)row * V_DIM;
#pragma unroll
                for (int nf = 0; nf < 8; nf++) {
                    float v0 = acc[mf][nf][h * 2 + 0];
                    float v1 = acc[mf][nf][h * 2 + 1];
                    int col = bn + wn + nf * 8 + cp * 2;
                    if (cv[nf][0]) { __stcs(&C[rowbase + col], v0);     m = fmaxf(m, v0); }
                    if (cv[nf][1]) { __stcs(&C[rowbase + col + 1], v1); m = fmaxf(m, v1); }
                }
                // warp-local row reduce over the 4 cp lanes
                m = fmaxf(m, __shfl_xor_sync(0xFFFFFFFF, m, 1));
                m = fmaxf(m, __shfl_xor_sync(0xFFFFFFFF, m, 2));
                float s = 0.0f;
#pragma unroll
                for (int nf = 0; nf < 8; nf++) {
                    if (cv[nf][0]) s += __expf(acc[mf][nf][h * 2 + 0] - m);
                    if (cv[nf][1]) s += __expf(acc[mf][nf][h * 2 + 1] - m);
                }
                s += __shfl_xor_sync(0xFFFFFFFF, s, 1);
                s += __shfl_xor_sync(0xFFFFFFFF, s, 2);
                if (cp == 0) {
                    g_pmax[(size_t)row * NB4 + pcol] = m;
                    g_psum[(size_t)row * NB4 + pcol] = s;
                }
            }
        }
        __syncthreads();   // A-buffer reuse barrier
    }
}

// ---------------------------------------------------------------------------
// Kernel 5: reduce partial (max,sum) -> lse per row
// ---------------------------------------------------------------------------
__global__ void reduce_lse_kernel() {
    int b = blockIdx.x;
    int t = threadIdx.x;        // 128
    float m = -INFINITY, s = 0.0f;
    for (int i = t; i < NB4; i += 128) {
        float pm = g_pmax[(size_t)b * NB4 + i];
        float ps = g_psum[(size_t)b * NB4 + i];
        if (pm > m) { s = s * __expf(m - pm) + ps; m = pm; }
        else        { s += ps * __expf(pm - m); }
    }
#pragma unroll
    for (int o = 16; o > 0; o >>= 1) {
        float m2 = __shfl_xor_sync(0xFFFFFFFF, m, o);
        float s2 = __shfl_xor_sync(0xFFFFFFFF, s, o);
        float M = fmaxf(m, m2);
        s = s * __expf(m - M) + s2 * __expf(m2 - M);
        m = M;
    }
    __shared__ float sm[4], ss[4];
    if ((t & 31) == 0) { sm[t >> 5] = m; ss[t >> 5] = s; }
    __syncthreads();
    if (t == 0) {
        m = sm[0]; s = ss[0];
#pragma unroll
        for (int w = 1; w < 4; w++) {
            float M = fmaxf(m, sm[w]);
            s = s * __expf(m - M) + ss[w] * __expf(sm[w] - M);
            m = M;
        }
        g_lse[b] = m + logf(s);
    }
}

// ---------------------------------------------------------------------------
// Kernel 6: out -= lse[row]  (flat float4, streaming)
// ---------------------------------------------------------------------------
__global__ void sub_lse_kernel(float4* __restrict__ C) {
    unsigned i = blockIdx.x * 256u + threadIdx.x;   // < N4
    float4 v = __ldcs(&C[i]);
    unsigned base = i * 4u;
    v.x -= g_lse[ base      / V_DIM];
    v.y -= g_lse[(base + 1) / V_DIM];
    v.z -= g_lse[(base + 2) / V_DIM];
    v.w -= g_lse[(base + 3) / V_DIM];
    __stcs(&C[i], v);
}

// ---------------------------------------------------------------------------
extern "C" void kernel_launch(void* const* d_in, const int* in_sizes, int n_in,
                              void* d_out, int out_size) {
    const float* xs     = (const float*)d_in[0];
    const float* metric = (const float*)d_in[1];
    const float* EMBEDM = (const float*)d_in[2];
    const float* NEG    = (const float*)d_in[3];
    float* out = (float*)d_out;

    cudaFuncSetAttribute(gemm_hmma_kernel,
                         cudaFuncAttributeMaxDynamicSharedMemorySize, SMEM_TOTAL);

    find_ids_kernel<<<N4 / 256, 256>>>((const float4*)xs);
    gather_project_kernel<<<B_DIM, E_DIM>>>(EMBEDM, metric);
    convert_neg_kernel<<<(V_DIM * E_DIM / 4 + 255) / 256, 256>>>((const float4*)NEG);

    gemm_hmma_kernel<<<dim3(NBX, 4), 256, SMEM_TOTAL>>>(out);

    reduce_lse_kernel<<<B_DIM, 128>>>();
    sub_lse_kernel<<<N4 / 256, 256>>>((float4*)out);
}